// round 12
// baseline (speedup 1.0000x reference)
#include <cuda_runtime.h>
#include <math.h>

#define BB 8
#define CC 512
#define HH 75
#define WW 100
#define PP 7500
#define KK 2000
#define FF 128

typedef unsigned long long u64;
typedef unsigned int u32;

#define CLIP(x) fminf(fmaxf((x), 0.0f), 6.0f)

// pack two f32 into bf16x2: result.lo = lo_elem, result.hi = hi_elem
__device__ __forceinline__ u32 packbf2(float lo_elem, float hi_elem) {
    u32 r;
    asm("cvt.rn.bf16x2.f32 %0, %1, %2;" : "=r"(r) : "f"(hi_elem), "f"(lo_elem));
    return r;
}
__device__ __forceinline__ float bf_lo(u32 p) { return __uint_as_float(p << 16); }
__device__ __forceinline__ float bf_hi(u32 p) { return __uint_as_float(p & 0xFFFF0000u); }

__device__ __forceinline__ void mma16(float* d, u32 a0, u32 a1, u32 a2, u32 a3,
                                      u32 b0, u32 b1) {
    asm volatile(
        "mma.sync.aligned.m16n8k16.row.col.f32.bf16.bf16.f32 "
        "{%0,%1,%2,%3}, {%4,%5,%6,%7}, {%8,%9}, {%0,%1,%2,%3};"
        : "+f"(d[0]), "+f"(d[1]), "+f"(d[2]), "+f"(d[3])
        : "r"(a0), "r"(a1), "r"(a2), "r"(a3), "r"(b0), "r"(b1));
}

// ---------------- scratch ----------------
__device__ int   g_sorted[BB * KK];
__device__ int   g_rank[BB * PP];
__device__ int   g_nbr[BB * KK * 9];
__device__ int   g_pix[BB * KK];
__device__ float g_t1[BB * KK * FF];
__device__ float g_x1[BB * KK * FF];
__device__ float g_s2[BB * KK * FF];
// bf16 hi/lo fragment tables: entry = {b0_hi, b1_hi, b0_lo, b1_lo}
__device__ uint4 g_w1f4[32 * 16 * 32];
__device__ uint4 g_w2f4[8 * 16 * 32];

// ---------------- block-wide exclusive scan (blockDim == 1024) ----------------
__device__ __forceinline__ int block_excl_scan(int v, int* warp_sums, int tid) {
    int lane = tid & 31, wid = tid >> 5;
    int x = v;
#pragma unroll
    for (int o = 1; o < 32; o <<= 1) {
        int y = __shfl_up_sync(0xFFFFFFFFu, x, o);
        if (lane >= o) x += y;
    }
    if (lane == 31) warp_sums[wid] = x;
    __syncthreads();
    if (wid == 0) {
        int s = warp_sums[lane];
        int orig = s;
#pragma unroll
        for (int o = 1; o < 32; o <<= 1) {
            int y = __shfl_up_sync(0xFFFFFFFFu, s, o);
            if (lane >= o) s += y;
        }
        warp_sums[lane] = s - orig;
    }
    __syncthreads();
    return (x - v) + warp_sums[wid];
}

// ---------------- weight split helper ----------------
__device__ __forceinline__ uint4 split_frag(const float* w, int k0, int n) {
    float v0 = w[k0 * FF + n];
    float v1 = w[(k0 + 1) * FF + n];
    float v2 = w[(k0 + 8) * FF + n];
    float v3 = w[(k0 + 9) * FF + n];
    u32 b0h = packbf2(v0, v1);
    u32 b1h = packbf2(v2, v3);
    u32 b0l = packbf2(v0 - bf_lo(b0h), v1 - bf_hi(b0h));
    u32 b1l = packbf2(v2 - bf_lo(b1h), v3 - bf_hi(b1h));
    return make_uint4(b0h, b1h, b0l, b1l);
}

// ---------------- K1: setup = topk + nbr (blocks 0..7) | weight prep (blocks 8..27) ----------------
#define CAND_CAP 4096
__global__ void __launch_bounds__(1024) setup_kernel(const float* __restrict__ pred,
                                                     const float* __restrict__ w1,
                                                     const float* __restrict__ w2,
                                                     float* __restrict__ out_idx) {
    int tid = threadIdx.x;
    if (blockIdx.x >= 8) {
        int t = (blockIdx.x - 8) * 1024 + tid;
        if (t < 32 * 16 * 32) {
            int lane = t & 31;
            int ntg  = (t >> 5) & 15;
            int kb   = t >> 9;
            int n  = ntg * 8 + (lane >> 2);
            int k0 = kb * 16 + 2 * (lane & 3);
            g_w1f4[t] = split_frag(w1, k0, n);
        } else if (t < 32 * 16 * 32 + 8 * 16 * 32) {
            int t2 = t - 32 * 16 * 32;
            int lane = t2 & 31;
            int ntg  = (t2 >> 5) & 15;
            int kb   = t2 >> 9;
            int n  = ntg * 8 + (lane >> 2);
            int k0 = kb * 16 + 2 * (lane & 3);
            g_w2f4[t2] = split_frag(w2, k0, n);
        }
        return;
    }
    // ---- topk ----
    int b = blockIdx.x;
    const float* sc = pred + (size_t)b * 3 * PP;
    __shared__ unsigned keys[PP];
    __shared__ unsigned hist[256];
    __shared__ unsigned short cand[CAND_CAP];
    __shared__ int candN;
    __shared__ int sh_bin;
    __shared__ unsigned sh_r2;
    __shared__ int warp_sums[32];

    for (int i = tid; i < PP; i += 1024) {
        unsigned u = __float_as_uint(sc[i]);
        u = (u & 0x80000000u) ? ~u : (u | 0x80000000u);
        keys[i] = u;
    }
    for (int i = tid; i < PP; i += 1024) g_rank[b * PP + i] = -1;
    if (tid == 0) candN = 0;
    __syncthreads();

    // pass 0 over all keys
    unsigned prefix = 0, r = KK;
    {
        for (int i = tid; i < 256; i += 1024) hist[i] = 0;
        __syncthreads();
        for (int i = tid; i < PP; i += 1024)
            atomicAdd(&hist[keys[i] >> 24], 1u);
        __syncthreads();
        int v = (tid < 256) ? (int)hist[255 - tid] : 0;
        int ex = block_excl_scan(v, warp_sums, tid);
        if (tid < 256 && ex < (int)r && ex + v >= (int)r) {
            sh_bin = 255 - tid;
            sh_r2  = r - (unsigned)ex;
        }
        __syncthreads();
        prefix = ((unsigned)sh_bin) << 24;
        r = sh_r2;
        __syncthreads();
    }
    // compact candidates matching pass-0 bin
    {
        unsigned bin0 = prefix >> 24;
        for (int i = tid; i < PP; i += 1024) {
            if ((keys[i] >> 24) == bin0) {
                int p = atomicAdd(&candN, 1);
                if (p < CAND_CAP) cand[p] = (unsigned short)i;
            }
        }
        __syncthreads();
    }
    int useCand = (candN <= CAND_CAP);
    int nScan = useCand ? candN : PP;

    // passes 1..3 over compacted candidates
#pragma unroll
    for (int pass = 1; pass < 4; ++pass) {
        int shift = 24 - 8 * pass;
        unsigned mask_hi = 0xFFFFFFFFu << (shift + 8);
        for (int i = tid; i < 256; i += 1024) hist[i] = 0;
        __syncthreads();
        for (int idx = tid; idx < nScan; idx += 1024) {
            int i = useCand ? (int)cand[idx] : idx;
            unsigned u = keys[i];
            if ((u & mask_hi) == prefix)
                atomicAdd(&hist[(u >> shift) & 255u], 1u);
        }
        __syncthreads();
        int v = (tid < 256) ? (int)hist[255 - tid] : 0;
        int ex = block_excl_scan(v, warp_sums, tid);
        if (tid < 256 && ex < (int)r && ex + v >= (int)r) {
            sh_bin = 255 - tid;
            sh_r2  = r - (unsigned)ex;
        }
        __syncthreads();
        prefix |= ((unsigned)sh_bin) << shift;
        r = sh_r2;
        __syncthreads();
    }
    unsigned T = prefix;

    int start = tid * 8;
    int cnt_gt = 0, cnt_eq = 0;
#pragma unroll
    for (int k = 0; k < 8; ++k) {
        int i = start + k;
        if (i < PP) {
            unsigned u = keys[i];
            cnt_gt += (u > T);
            cnt_eq += (u == T);
        }
    }
    int base_eq = block_excl_scan(cnt_eq, warp_sums, tid);
    __syncthreads();
    int need = (int)r - base_eq;
    if (need < 0) need = 0;
    if (need > cnt_eq) need = cnt_eq;
    int my_sel = cnt_gt + need;
    int base_out = block_excl_scan(my_sel, warp_sums, tid);

    int pos = base_out, eqr = base_eq;
    for (int k = 0; k < 8; ++k) {
        int i = start + k;
        if (i >= PP) break;
        unsigned u = keys[i];
        bool sel = (u > T);
        if (u == T) { if (eqr < (int)r) sel = true; eqr++; }
        if (sel) {
            g_sorted[b * KK + pos] = i;
            if (out_idx) out_idx[b * KK + pos] = (float)i;
            g_rank[b * PP + i] = pos;
            g_pix[b * KK + pos] = (i % HH) * WW + (i / HH);
            pos++;
        }
    }
    __syncthreads();

    // ---- nbr (fused) ----
    for (int i = tid; i < KK; i += 1024) {
        int s = g_sorted[b * KK + i];
        int py = s / WW, px = s % WW;
        const int* rk = g_rank + b * PP;
        int* nb = g_nbr + (b * KK + i) * 9;
#pragma unroll
        for (int q = 0; q < 9; ++q) {
            int dy = q / 3 - 1, dx = q % 3 - 1;
            int ny = py + dy, nx = px + dx;
            int v = -1;
            if (ny >= 0 && ny < HH && nx >= 0 && nx < WW)
                v = rk[ny * WW + nx];
            nb[q] = v;
        }
    }
}

// ---------------- K2: fused gather + GEMM1, bf16 3-term split, 2-ahead prefetch ----------------
#define AST 72
__global__ void __launch_bounds__(256, 2) gemm1_mma(const float* __restrict__ feat) {
    __shared__ u32 AhS[2][8 * AST];
    __shared__ u32 AlS[2][8 * AST];
    __shared__ int pixS[64];
    int b = blockIdx.y, i0 = blockIdx.x * 64;
    int tid = threadIdx.x;
    int lane = tid & 31, warp = tid >> 5;
    int wm = warp & 1, wn = warp >> 1;
    int lm = tid & 63, lcg = tid >> 6;

    if (tid < 64) {
        int gi = i0 + tid;
        pixS[tid] = (gi < KK) ? g_pix[b * KK + gi] : 0;
    }
    __syncthreads();

    const float* fb = feat + (size_t)b * CC * PP;
    float acc[2][4][4];
#pragma unroll
    for (int mt = 0; mt < 2; ++mt)
#pragma unroll
        for (int nt = 0; nt < 4; ++nt)
#pragma unroll
            for (int e = 0; e < 4; ++e) acc[mt][nt][e] = 0.0f;

    int mypix = pixS[lm];
    float pf[2][4];

    // prologue: stage 0 straight to smem buffer 0
    {
        const float* fp = fb + (size_t)(lcg * 4) * PP + mypix;
        float v0 = CLIP(fp[0]);
        float v1 = CLIP(fp[PP]);
        float v2 = CLIP(fp[2 * PP]);
        float v3 = CLIP(fp[3 * PP]);
        u32 h01 = packbf2(v0, v1), h23 = packbf2(v2, v3);
        AhS[0][(lcg * 2 + 0) * AST + lm] = h01;
        AhS[0][(lcg * 2 + 1) * AST + lm] = h23;
        AlS[0][(lcg * 2 + 0) * AST + lm] = packbf2(v0 - bf_lo(h01), v1 - bf_hi(h01));
        AlS[0][(lcg * 2 + 1) * AST + lm] = packbf2(v2 - bf_lo(h23), v3 - bf_hi(h23));
    }
    // prologue: stage 1 into pf[1]
    {
        const float* fp = fb + (size_t)(16 + lcg * 4) * PP + mypix;
        pf[1][0] = CLIP(fp[0]);
        pf[1][1] = CLIP(fp[PP]);
        pf[1][2] = CLIP(fp[2 * PP]);
        pf[1][3] = CLIP(fp[3 * PP]);
    }
    __syncthreads();

    int r4 = lane >> 2, c4 = lane & 3;

#pragma unroll 2
    for (int s = 0; s < 32; ++s) {
        int cur = s & 1;
        // issue gathers for stage s+2 into pf[cur]
        if (s < 30) {
            const float* fp = fb + (size_t)((s + 2) * 16 + lcg * 4) * PP + mypix;
            pf[cur][0] = CLIP(fp[0]);
            pf[cur][1] = CLIP(fp[PP]);
            pf[cur][2] = CLIP(fp[2 * PP]);
            pf[cur][3] = CLIP(fp[3 * PP]);
        }
        uint4 bf[4];
#pragma unroll
        for (int nt = 0; nt < 4; ++nt)
            bf[nt] = g_w1f4[(s * 16 + wn * 4 + nt) * 32 + lane];

#pragma unroll
        for (int mt = 0; mt < 2; ++mt) {
            int mb = wm * 32 + mt * 16 + r4;
            u32 ah0 = AhS[cur][c4 * AST + mb];
            u32 ah1 = AhS[cur][c4 * AST + mb + 8];
            u32 ah2 = AhS[cur][(c4 + 4) * AST + mb];
            u32 ah3 = AhS[cur][(c4 + 4) * AST + mb + 8];
            u32 al0 = AlS[cur][c4 * AST + mb];
            u32 al1 = AlS[cur][c4 * AST + mb + 8];
            u32 al2 = AlS[cur][(c4 + 4) * AST + mb];
            u32 al3 = AlS[cur][(c4 + 4) * AST + mb + 8];
#pragma unroll
            for (int nt = 0; nt < 4; ++nt) {
                uint4 bb = bf[nt];
                mma16(acc[mt][nt], ah0, ah1, ah2, ah3, bb.x, bb.y);
                mma16(acc[mt][nt], ah0, ah1, ah2, ah3, bb.z, bb.w);
                mma16(acc[mt][nt], al0, al1, al2, al3, bb.x, bb.y);
            }
        }
        // store stage s+1 (held in pf[cur^1]) into smem buffer cur^1
        if (s < 31) {
            float v0 = pf[cur ^ 1][0], v1 = pf[cur ^ 1][1];
            float v2 = pf[cur ^ 1][2], v3 = pf[cur ^ 1][3];
            u32 h01 = packbf2(v0, v1), h23 = packbf2(v2, v3);
            AhS[cur ^ 1][(lcg * 2 + 0) * AST + lm] = h01;
            AhS[cur ^ 1][(lcg * 2 + 1) * AST + lm] = h23;
            AlS[cur ^ 1][(lcg * 2 + 0) * AST + lm] = packbf2(v0 - bf_lo(h01), v1 - bf_hi(h01));
            AlS[cur ^ 1][(lcg * 2 + 1) * AST + lm] = packbf2(v2 - bf_lo(h23), v3 - bf_hi(h23));
        }
        __syncthreads();
    }

    float* t1b = g_t1 + b * KK * FF;
#pragma unroll
    for (int mt = 0; mt < 2; ++mt) {
#pragma unroll
        for (int nt = 0; nt < 4; ++nt) {
            int m = wm * 32 + mt * 16 + r4;
            int n = wn * 32 + nt * 8 + 2 * c4;
            int gi = i0 + m;
            if (gi < KK)
                *(float2*)&t1b[gi * FF + n] = make_float2(acc[mt][nt][0], acc[mt][nt][1]);
            int gi8 = gi + 8;
            if (gi8 < KK)
                *(float2*)&t1b[gi8 * FF + n] = make_float2(acc[mt][nt][2], acc[mt][nt][3]);
        }
    }
}

// ---------------- K3: x1 = A @ t1 + b1 (2 rows per thread) ----------------
__global__ void __launch_bounds__(256) x1_kernel(const float* __restrict__ b1) {
    int wid = threadIdx.x >> 5;
    int lane = threadIdx.x & 31;
    int r0 = blockIdx.x * 16 + wid * 2;
    int b = r0 / KK;
    const float* t1b = g_t1 + b * KK * FF;
#pragma unroll
    for (int rr = 0; rr < 2; ++rr) {
        int r = r0 + rr;
        int i = r % KK;
        const int* nb = g_nbr + r * 9;
        float4 s = *(const float4*)&b1[i * FF + lane * 4];
#pragma unroll
        for (int q = 0; q < 9; ++q) {
            int j = nb[q];
            if (j >= 0) {
                float4 t = *(const float4*)&t1b[j * FF + lane * 4];
                s.x += t.x; s.y += t.y; s.z += t.z; s.w += t.w;
            }
        }
        *(float4*)&g_x1[r * FF + lane * 4] = s;
    }
}

// ---------------- K4: s2 = A @ x1 (2 rows per thread) ----------------
__global__ void __launch_bounds__(256) s2_kernel() {
    int wid = threadIdx.x >> 5;
    int lane = threadIdx.x & 31;
    int r0 = blockIdx.x * 16 + wid * 2;
    int b = r0 / KK;
    const float* x1b = g_x1 + b * KK * FF;
#pragma unroll
    for (int rr = 0; rr < 2; ++rr) {
        int r = r0 + rr;
        const int* nb = g_nbr + r * 9;
        float4 s = make_float4(0.f, 0.f, 0.f, 0.f);
#pragma unroll
        for (int q = 0; q < 9; ++q) {
            int j = nb[q];
            if (j >= 0) {
                float4 t = *(const float4*)&x1b[j * FF + lane * 4];
                s.x += t.x; s.y += t.y; s.z += t.z; s.w += t.w;
            }
        }
        *(float4*)&g_s2[r * FF + lane * 4] = s;
    }
}

// ---------------- K5: out = tanh(s2 @ w2 + b2 + x1), lean A-loader, bf16 3-term ----------------
__global__ void __launch_bounds__(256, 2) gemm2_mma(const float* __restrict__ b2,
                                                    float* __restrict__ out) {
    __shared__ u32 AhS[2][8 * AST];
    __shared__ u32 AlS[2][8 * AST];
    int b = blockIdx.y, i0 = blockIdx.x * 64;
    int tid = threadIdx.x;
    int lane = tid & 31, warp = tid >> 5;
    int wm = warp & 1, wn = warp >> 1;
    int lm = tid & 63, lcg = tid >> 6;

    const float* s2b = g_s2 + b * KK * FF;
    int gi_l = i0 + lm;
    int gi_c = (gi_l < KK) ? gi_l : (KK - 1);

    float acc[2][4][4];
#pragma unroll
    for (int mt = 0; mt < 2; ++mt)
#pragma unroll
        for (int nt = 0; nt < 4; ++nt)
#pragma unroll
            for (int e = 0; e < 4; ++e) acc[mt][nt][e] = 0.0f;

    // prologue stage 0
    {
        float4 v = *(const float4*)&s2b[gi_c * FF + lcg * 4];
        u32 h01 = packbf2(v.x, v.y), h23 = packbf2(v.z, v.w);
        AhS[0][(lcg * 2 + 0) * AST + lm] = h01;
        AhS[0][(lcg * 2 + 1) * AST + lm] = h23;
        AlS[0][(lcg * 2 + 0) * AST + lm] = packbf2(v.x - bf_lo(h01), v.y - bf_hi(h01));
        AlS[0][(lcg * 2 + 1) * AST + lm] = packbf2(v.z - bf_lo(h23), v.w - bf_hi(h23));
    }
    __syncthreads();

    int r4 = lane >> 2, c4 = lane & 3;

#pragma unroll 1
    for (int s = 0; s < 8; ++s) {
        int cur = s & 1;
        float4 v;
        if (s < 7)
            v = *(const float4*)&s2b[gi_c * FF + (s + 1) * 16 + lcg * 4];
        uint4 bf[4];
#pragma unroll
        for (int nt = 0; nt < 4; ++nt)
            bf[nt] = g_w2f4[(s * 16 + wn * 4 + nt) * 32 + lane];

#pragma unroll
        for (int mt = 0; mt < 2; ++mt) {
            int mb = wm * 32 + mt * 16 + r4;
            u32 ah0 = AhS[cur][c4 * AST + mb];
            u32 ah1 = AhS[cur][c4 * AST + mb + 8];
            u32 ah2 = AhS[cur][(c4 + 4) * AST + mb];
            u32 ah3 = AhS[cur][(c4 + 4) * AST + mb + 8];
            u32 al0 = AlS[cur][c4 * AST + mb];
            u32 al1 = AlS[cur][c4 * AST + mb + 8];
            u32 al2 = AlS[cur][(c4 + 4) * AST + mb];
            u32 al3 = AlS[cur][(c4 + 4) * AST + mb + 8];
#pragma unroll
            for (int nt = 0; nt < 4; ++nt) {
                uint4 bb = bf[nt];
                mma16(acc[mt][nt], ah0, ah1, ah2, ah3, bb.x, bb.y);
                mma16(acc[mt][nt], ah0, ah1, ah2, ah3, bb.z, bb.w);
                mma16(acc[mt][nt], al0, al1, al2, al3, bb.x, bb.y);
            }
        }
        if (s < 7) {
            int nb = (s + 1) & 1;
            u32 h01 = packbf2(v.x, v.y), h23 = packbf2(v.z, v.w);
            AhS[nb][(lcg * 2 + 0) * AST + lm] = h01;
            AhS[nb][(lcg * 2 + 1) * AST + lm] = h23;
            AlS[nb][(lcg * 2 + 0) * AST + lm] = packbf2(v.x - bf_lo(h01), v.y - bf_hi(h01));
            AlS[nb][(lcg * 2 + 1) * AST + lm] = packbf2(v.z - bf_lo(h23), v.w - bf_hi(h23));
        }
        __syncthreads();
    }

    const float* x1b = g_x1 + b * KK * FF;
#pragma unroll
    for (int mt = 0; mt < 2; ++mt) {
#pragma unroll
        for (int nt = 0; nt < 4; ++nt) {
            int m = wm * 32 + mt * 16 + r4;
            int n = wn * 32 + nt * 8 + 2 * c4;
#pragma unroll
            for (int half = 0; half < 2; ++half) {
                int gi = i0 + m + half * 8;
                if (gi < KK) {
                    int base = gi * FF + n;
                    float2 bb = *(const float2*)&b2[base];
                    float2 xx = *(const float2*)&x1b[base];
                    float2 o;
                    o.x = tanhf(acc[mt][nt][half * 2 + 0] + bb.x + xx.x);
                    o.y = tanhf(acc[mt][nt][half * 2 + 1] + bb.y + xx.y);
                    *(float2*)&out[(size_t)b * KK * FF + base] = o;
                }
            }
        }
    }
}

// ---------------- launch ----------------
extern "C" void kernel_launch(void* const* d_in, const int* in_sizes, int n_in,
                              void* d_out, int out_size) {
    const float* feat = (const float*)d_in[0];
    const float* pred = (const float*)d_in[1];
    const float* w1   = (const float*)d_in[2];
    const float* b1   = (const float*)d_in[3];
    const float* w2   = (const float*)d_in[4];
    const float* b2   = (const float*)d_in[5];
    float* out = (float*)d_out;

    const int feat_elems = BB * KK * FF;
    float* out_idx = (out_size >= feat_elems + BB * KK) ? (out + feat_elems) : (float*)0;

    setup_kernel<<<28, 1024>>>(pred, w1, w2, out_idx);
    {
        dim3 grid((KK + 63) / 64, BB);
        gemm1_mma<<<grid, 256>>>(feat);
    }
    x1_kernel<<<BB * KK / 16, 256>>>(b1);
    s2_kernel<<<BB * KK / 16, 256>>>();
    {
        dim3 grid((KK + 63) / 64, BB);
        gemm2_mma<<<grid, 256>>>(b2, out);
    }
}

// round 14
// speedup vs baseline: 1.0203x; 1.0203x over previous
#include <cuda_runtime.h>
#include <math.h>

#define BB 8
#define CC 512
#define HH 75
#define WW 100
#define PP 7500
#define KK 2000
#define FF 128

typedef unsigned long long u64;
typedef unsigned int u32;

#define CLIP(x) fminf(fmaxf((x), 0.0f), 6.0f)

#define GDC_WAIT()   asm volatile("griddepcontrol.wait;" ::: "memory")
#define GDC_LAUNCH() asm volatile("griddepcontrol.launch_dependents;" ::: "memory")

// pack two f32 into bf16x2: result.lo = lo_elem, result.hi = hi_elem
__device__ __forceinline__ u32 packbf2(float lo_elem, float hi_elem) {
    u32 r;
    asm("cvt.rn.bf16x2.f32 %0, %1, %2;" : "=r"(r) : "f"(hi_elem), "f"(lo_elem));
    return r;
}
__device__ __forceinline__ float bf_lo(u32 p) { return __uint_as_float(p << 16); }
__device__ __forceinline__ float bf_hi(u32 p) { return __uint_as_float(p & 0xFFFF0000u); }

__device__ __forceinline__ void mma16(float* d, u32 a0, u32 a1, u32 a2, u32 a3,
                                      u32 b0, u32 b1) {
    asm volatile(
        "mma.sync.aligned.m16n8k16.row.col.f32.bf16.bf16.f32 "
        "{%0,%1,%2,%3}, {%4,%5,%6,%7}, {%8,%9}, {%0,%1,%2,%3};"
        : "+f"(d[0]), "+f"(d[1]), "+f"(d[2]), "+f"(d[3])
        : "r"(a0), "r"(a1), "r"(a2), "r"(a3), "r"(b0), "r"(b1));
}

// ---------------- scratch ----------------
__device__ int   g_sorted[BB * KK];
__device__ int   g_rank[BB * PP];
__device__ int   g_nbr[BB * KK * 9];
__device__ int   g_pix[BB * KK];
__device__ float g_t1[BB * KK * FF];
__device__ float g_x1[BB * KK * FF];
__device__ float g_s2[BB * KK * FF];
// bf16 hi/lo fragment tables: entry = {b0_hi, b1_hi, b0_lo, b1_lo}
__device__ uint4 g_w1f4[32 * 16 * 32];
__device__ uint4 g_w2f4[8 * 16 * 32];

// ---------------- block-wide exclusive scan (blockDim == 1024) ----------------
__device__ __forceinline__ int block_excl_scan(int v, int* warp_sums, int tid) {
    int lane = tid & 31, wid = tid >> 5;
    int x = v;
#pragma unroll
    for (int o = 1; o < 32; o <<= 1) {
        int y = __shfl_up_sync(0xFFFFFFFFu, x, o);
        if (lane >= o) x += y;
    }
    if (lane == 31) warp_sums[wid] = x;
    __syncthreads();
    if (wid == 0) {
        int s = warp_sums[lane];
        int orig = s;
#pragma unroll
        for (int o = 1; o < 32; o <<= 1) {
            int y = __shfl_up_sync(0xFFFFFFFFu, s, o);
            if (lane >= o) s += y;
        }
        warp_sums[lane] = s - orig;
    }
    __syncthreads();
    return (x - v) + warp_sums[wid];
}

// ---------------- weight split helper ----------------
__device__ __forceinline__ uint4 split_frag(const float* w, int k0, int n) {
    float v0 = w[k0 * FF + n];
    float v1 = w[(k0 + 1) * FF + n];
    float v2 = w[(k0 + 8) * FF + n];
    float v3 = w[(k0 + 9) * FF + n];
    u32 b0h = packbf2(v0, v1);
    u32 b1h = packbf2(v2, v3);
    u32 b0l = packbf2(v0 - bf_lo(b0h), v1 - bf_hi(b0h));
    u32 b1l = packbf2(v2 - bf_lo(b1h), v3 - bf_hi(b1h));
    return make_uint4(b0h, b1h, b0l, b1l);
}

// ---------------- K1: setup = topk + nbr (blocks 0..7) | weight prep (blocks 8..27) ----------------
#define CAND_CAP 4096
__global__ void __launch_bounds__(1024) setup_kernel(const float* __restrict__ pred,
                                                     const float* __restrict__ w1,
                                                     const float* __restrict__ w2,
                                                     float* __restrict__ out_idx) {
    int tid = threadIdx.x;
    if (blockIdx.x >= 8) {
        int t = (blockIdx.x - 8) * 1024 + tid;
        if (t < 32 * 16 * 32) {
            int lane = t & 31;
            int ntg  = (t >> 5) & 15;
            int kb   = t >> 9;
            int n  = ntg * 8 + (lane >> 2);
            int k0 = kb * 16 + 2 * (lane & 3);
            g_w1f4[t] = split_frag(w1, k0, n);
        } else if (t < 32 * 16 * 32 + 8 * 16 * 32) {
            int t2 = t - 32 * 16 * 32;
            int lane = t2 & 31;
            int ntg  = (t2 >> 5) & 15;
            int kb   = t2 >> 9;
            int n  = ntg * 8 + (lane >> 2);
            int k0 = kb * 16 + 2 * (lane & 3);
            g_w2f4[t2] = split_frag(w2, k0, n);
        }
        GDC_LAUNCH();
        return;
    }
    // ---- topk ----
    int b = blockIdx.x;
    const float* sc = pred + (size_t)b * 3 * PP;
    __shared__ unsigned keys[PP];
    __shared__ unsigned hist[256];
    __shared__ unsigned short cand[CAND_CAP];
    __shared__ int candN;
    __shared__ int sh_bin;
    __shared__ unsigned sh_r2;
    __shared__ int warp_sums[32];

    for (int i = tid; i < PP; i += 1024) {
        unsigned u = __float_as_uint(sc[i]);
        u = (u & 0x80000000u) ? ~u : (u | 0x80000000u);
        keys[i] = u;
    }
    for (int i = tid; i < PP; i += 1024) g_rank[b * PP + i] = -1;
    if (tid == 0) candN = 0;
    __syncthreads();

    // pass 0 over all keys
    unsigned prefix = 0, r = KK;
    {
        for (int i = tid; i < 256; i += 1024) hist[i] = 0;
        __syncthreads();
        for (int i = tid; i < PP; i += 1024)
            atomicAdd(&hist[keys[i] >> 24], 1u);
        __syncthreads();
        int v = (tid < 256) ? (int)hist[255 - tid] : 0;
        int ex = block_excl_scan(v, warp_sums, tid);
        if (tid < 256 && ex < (int)r && ex + v >= (int)r) {
            sh_bin = 255 - tid;
            sh_r2  = r - (unsigned)ex;
        }
        __syncthreads();
        prefix = ((unsigned)sh_bin) << 24;
        r = sh_r2;
        __syncthreads();
    }
    // compact candidates matching pass-0 bin
    {
        unsigned bin0 = prefix >> 24;
        for (int i = tid; i < PP; i += 1024) {
            if ((keys[i] >> 24) == bin0) {
                int p = atomicAdd(&candN, 1);
                if (p < CAND_CAP) cand[p] = (unsigned short)i;
            }
        }
        __syncthreads();
    }
    int useCand = (candN <= CAND_CAP);
    int nScan = useCand ? candN : PP;

    // passes 1..3 over compacted candidates
#pragma unroll
    for (int pass = 1; pass < 4; ++pass) {
        int shift = 24 - 8 * pass;
        unsigned mask_hi = 0xFFFFFFFFu << (shift + 8);
        for (int i = tid; i < 256; i += 1024) hist[i] = 0;
        __syncthreads();
        for (int idx = tid; idx < nScan; idx += 1024) {
            int i = useCand ? (int)cand[idx] : idx;
            unsigned u = keys[i];
            if ((u & mask_hi) == prefix)
                atomicAdd(&hist[(u >> shift) & 255u], 1u);
        }
        __syncthreads();
        int v = (tid < 256) ? (int)hist[255 - tid] : 0;
        int ex = block_excl_scan(v, warp_sums, tid);
        if (tid < 256 && ex < (int)r && ex + v >= (int)r) {
            sh_bin = 255 - tid;
            sh_r2  = r - (unsigned)ex;
        }
        __syncthreads();
        prefix |= ((unsigned)sh_bin) << shift;
        r = sh_r2;
        __syncthreads();
    }
    unsigned T = prefix;

    int start = tid * 8;
    int cnt_gt = 0, cnt_eq = 0;
#pragma unroll
    for (int k = 0; k < 8; ++k) {
        int i = start + k;
        if (i < PP) {
            unsigned u = keys[i];
            cnt_gt += (u > T);
            cnt_eq += (u == T);
        }
    }
    int base_eq = block_excl_scan(cnt_eq, warp_sums, tid);
    __syncthreads();
    int need = (int)r - base_eq;
    if (need < 0) need = 0;
    if (need > cnt_eq) need = cnt_eq;
    int my_sel = cnt_gt + need;
    int base_out = block_excl_scan(my_sel, warp_sums, tid);

    int pos = base_out, eqr = base_eq;
    for (int k = 0; k < 8; ++k) {
        int i = start + k;
        if (i >= PP) break;
        unsigned u = keys[i];
        bool sel = (u > T);
        if (u == T) { if (eqr < (int)r) sel = true; eqr++; }
        if (sel) {
            g_sorted[b * KK + pos] = i;
            if (out_idx) out_idx[b * KK + pos] = (float)i;
            g_rank[b * PP + i] = pos;
            g_pix[b * KK + pos] = (i % HH) * WW + (i / HH);
            pos++;
        }
    }
    __syncthreads();

    // ---- nbr (fused) ----
    for (int i = tid; i < KK; i += 1024) {
        int s = g_sorted[b * KK + i];
        int py = s / WW, px = s % WW;
        const int* rk = g_rank + b * PP;
        int* nb = g_nbr + (b * KK + i) * 9;
#pragma unroll
        for (int q = 0; q < 9; ++q) {
            int dy = q / 3 - 1, dx = q % 3 - 1;
            int ny = py + dy, nx = px + dx;
            int v = -1;
            if (ny >= 0 && ny < HH && nx >= 0 && nx < WW)
                v = rk[ny * WW + nx];
            nb[q] = v;
        }
    }
    GDC_LAUNCH();
}

// ---------------- K2: fused gather + GEMM1, bf16 3-term split, prefetched ----------------
#define AST 72
__global__ void __launch_bounds__(256, 2) gemm1_mma(const float* __restrict__ feat) {
    GDC_WAIT();
    __shared__ u32 AhS[2][8 * AST];
    __shared__ u32 AlS[2][8 * AST];
    __shared__ int pixS[64];
    int b = blockIdx.y, i0 = blockIdx.x * 64;
    int tid = threadIdx.x;
    int lane = tid & 31, warp = tid >> 5;
    int wm = warp & 1, wn = warp >> 1;
    int lm = tid & 63, lcg = tid >> 6;

    if (tid < 64) {
        int gi = i0 + tid;
        pixS[tid] = (gi < KK) ? g_pix[b * KK + gi] : 0;
    }
    __syncthreads();

    const float* fb = feat + (size_t)b * CC * PP;
    float acc[2][4][4];
#pragma unroll
    for (int mt = 0; mt < 2; ++mt)
#pragma unroll
        for (int nt = 0; nt < 4; ++nt)
#pragma unroll
            for (int e = 0; e < 4; ++e) acc[mt][nt][e] = 0.0f;

    int mypix = pixS[lm];
    float pf[2][4];

    // prologue: stage 0 straight to smem buffer 0
    {
        const float* fp = fb + (size_t)(lcg * 4) * PP + mypix;
        float v0 = CLIP(fp[0]);
        float v1 = CLIP(fp[PP]);
        float v2 = CLIP(fp[2 * PP]);
        float v3 = CLIP(fp[3 * PP]);
        u32 h01 = packbf2(v0, v1), h23 = packbf2(v2, v3);
        AhS[0][(lcg * 2 + 0) * AST + lm] = h01;
        AhS[0][(lcg * 2 + 1) * AST + lm] = h23;
        AlS[0][(lcg * 2 + 0) * AST + lm] = packbf2(v0 - bf_lo(h01), v1 - bf_hi(h01));
        AlS[0][(lcg * 2 + 1) * AST + lm] = packbf2(v2 - bf_lo(h23), v3 - bf_hi(h23));
    }
    // prologue: stage 1 into pf[1]
    {
        const float* fp = fb + (size_t)(16 + lcg * 4) * PP + mypix;
        pf[1][0] = CLIP(fp[0]);
        pf[1][1] = CLIP(fp[PP]);
        pf[1][2] = CLIP(fp[2 * PP]);
        pf[1][3] = CLIP(fp[3 * PP]);
    }
    // prologue: B frags for stage 0
    uint4 bfc[4];
#pragma unroll
    for (int nt = 0; nt < 4; ++nt)
        bfc[nt] = g_w1f4[(wn * 4 + nt) * 32 + lane];
    __syncthreads();

    int r4 = lane >> 2, c4 = lane & 3;

#pragma unroll 2
    for (int s = 0; s < 32; ++s) {
        int cur = s & 1;
        // issue gathers for stage s+2 into pf[cur]
        if (s < 30) {
            const float* fp = fb + (size_t)((s + 2) * 16 + lcg * 4) * PP + mypix;
            pf[cur][0] = CLIP(fp[0]);
            pf[cur][1] = CLIP(fp[PP]);
            pf[cur][2] = CLIP(fp[2 * PP]);
            pf[cur][3] = CLIP(fp[3 * PP]);
        }
        // prefetch B frags for stage s+1
        uint4 bfn[4];
        if (s < 31) {
#pragma unroll
            for (int nt = 0; nt < 4; ++nt)
                bfn[nt] = g_w1f4[((s + 1) * 16 + wn * 4 + nt) * 32 + lane];
        }

#pragma unroll
        for (int mt = 0; mt < 2; ++mt) {
            int mb = wm * 32 + mt * 16 + r4;
            u32 ah0 = AhS[cur][c4 * AST + mb];
            u32 ah1 = AhS[cur][c4 * AST + mb + 8];
            u32 ah2 = AhS[cur][(c4 + 4) * AST + mb];
            u32 ah3 = AhS[cur][(c4 + 4) * AST + mb + 8];
            u32 al0 = AlS[cur][c4 * AST + mb];
            u32 al1 = AlS[cur][c4 * AST + mb + 8];
            u32 al2 = AlS[cur][(c4 + 4) * AST + mb];
            u32 al3 = AlS[cur][(c4 + 4) * AST + mb + 8];
#pragma unroll
            for (int nt = 0; nt < 4; ++nt) {
                uint4 bb = bfc[nt];
                mma16(acc[mt][nt], ah0, ah1, ah2, ah3, bb.x, bb.y);
                mma16(acc[mt][nt], ah0, ah1, ah2, ah3, bb.z, bb.w);
                mma16(acc[mt][nt], al0, al1, al2, al3, bb.x, bb.y);
            }
        }
        // store stage s+1 (held in pf[cur^1]) into smem buffer cur^1
        if (s < 31) {
            float v0 = pf[cur ^ 1][0], v1 = pf[cur ^ 1][1];
            float v2 = pf[cur ^ 1][2], v3 = pf[cur ^ 1][3];
            u32 h01 = packbf2(v0, v1), h23 = packbf2(v2, v3);
            AhS[cur ^ 1][(lcg * 2 + 0) * AST + lm] = h01;
            AhS[cur ^ 1][(lcg * 2 + 1) * AST + lm] = h23;
            AlS[cur ^ 1][(lcg * 2 + 0) * AST + lm] = packbf2(v0 - bf_lo(h01), v1 - bf_hi(h01));
            AlS[cur ^ 1][(lcg * 2 + 1) * AST + lm] = packbf2(v2 - bf_lo(h23), v3 - bf_hi(h23));
        }
#pragma unroll
        for (int nt = 0; nt < 4; ++nt) bfc[nt] = bfn[nt];
        __syncthreads();
    }

    float* t1b = g_t1 + b * KK * FF;
#pragma unroll
    for (int mt = 0; mt < 2; ++mt) {
#pragma unroll
        for (int nt = 0; nt < 4; ++nt) {
            int m = wm * 32 + mt * 16 + r4;
            int n = wn * 32 + nt * 8 + 2 * c4;
            int gi = i0 + m;
            if (gi < KK)
                *(float2*)&t1b[gi * FF + n] = make_float2(acc[mt][nt][0], acc[mt][nt][1]);
            int gi8 = gi + 8;
            if (gi8 < KK)
                *(float2*)&t1b[gi8 * FF + n] = make_float2(acc[mt][nt][2], acc[mt][nt][3]);
        }
    }
    GDC_LAUNCH();
}

// ---------------- K3: x1 = A @ t1 + b1 (2 rows per thread) ----------------
__global__ void __launch_bounds__(256) x1_kernel(const float* __restrict__ b1) {
    int wid = threadIdx.x >> 5;
    int lane = threadIdx.x & 31;
    int r0 = blockIdx.x * 16 + wid * 2;
    int b = r0 / KK;
    // bias rows are independent of prior kernels; load before wait
    float4 s0 = *(const float4*)&b1[(r0 % KK) * FF + lane * 4];
    float4 s1 = *(const float4*)&b1[((r0 + 1) % KK) * FF + lane * 4];
    GDC_WAIT();
    const float* t1b = g_t1 + b * KK * FF;
#pragma unroll
    for (int rr = 0; rr < 2; ++rr) {
        int r = r0 + rr;
        const int* nb = g_nbr + r * 9;
        float4 s = rr ? s1 : s0;
#pragma unroll
        for (int q = 0; q < 9; ++q) {
            int j = nb[q];
            if (j >= 0) {
                float4 t = *(const float4*)&t1b[j * FF + lane * 4];
                s.x += t.x; s.y += t.y; s.z += t.z; s.w += t.w;
            }
        }
        *(float4*)&g_x1[r * FF + lane * 4] = s;
    }
    GDC_LAUNCH();
}

// ---------------- K4: s2 = A @ x1 (2 rows per thread) ----------------
__global__ void __launch_bounds__(256) s2_kernel() {
    GDC_WAIT();
    int wid = threadIdx.x >> 5;
    int lane = threadIdx.x & 31;
    int r0 = blockIdx.x * 16 + wid * 2;
    int b = r0 / KK;
    const float* x1b = g_x1 + b * KK * FF;
#pragma unroll
    for (int rr = 0; rr < 2; ++rr) {
        int r = r0 + rr;
        const int* nb = g_nbr + r * 9;
        float4 s = make_float4(0.f, 0.f, 0.f, 0.f);
#pragma unroll
        for (int q = 0; q < 9; ++q) {
            int j = nb[q];
            if (j >= 0) {
                float4 t = *(const float4*)&x1b[j * FF + lane * 4];
                s.x += t.x; s.y += t.y; s.z += t.z; s.w += t.w;
            }
        }
        *(float4*)&g_s2[r * FF + lane * 4] = s;
    }
    GDC_LAUNCH();
}

// ---------------- K5: out = tanh(s2 @ w2 + b2 + x1), bf16 3-term, prefetched ----------------
__global__ void __launch_bounds__(256, 2) gemm2_mma(const float* __restrict__ b2,
                                                    float* __restrict__ out) {
    GDC_WAIT();
    __shared__ u32 AhS[2][8 * AST];
    __shared__ u32 AlS[2][8 * AST];
    int b = blockIdx.y, i0 = blockIdx.x * 64;
    int tid = threadIdx.x;
    int lane = tid & 31, warp = tid >> 5;
    int wm = warp & 1, wn = warp >> 1;
    int lm = tid & 63, lcg = tid >> 6;

    const float* s2b = g_s2 + b * KK * FF;
    int gi_l = i0 + lm;
    int gi_c = (gi_l < KK) ? gi_l : (KK - 1);

    float acc[2][4][4];
#pragma unroll
    for (int mt = 0; mt < 2; ++mt)
#pragma unroll
        for (int nt = 0; nt < 4; ++nt)
#pragma unroll
            for (int e = 0; e < 4; ++e) acc[mt][nt][e] = 0.0f;

    // prologue stage 0
    {
        float4 v = *(const float4*)&s2b[gi_c * FF + lcg * 4];
        u32 h01 = packbf2(v.x, v.y), h23 = packbf2(v.z, v.w);
        AhS[0][(lcg * 2 + 0) * AST + lm] = h01;
        AhS[0][(lcg * 2 + 1) * AST + lm] = h23;
        AlS[0][(lcg * 2 + 0) * AST + lm] = packbf2(v.x - bf_lo(h01), v.y - bf_hi(h01));
        AlS[0][(lcg * 2 + 1) * AST + lm] = packbf2(v.z - bf_lo(h23), v.w - bf_hi(h23));
    }
    uint4 bfc[4];
#pragma unroll
    for (int nt = 0; nt < 4; ++nt)
        bfc[nt] = g_w2f4[(wn * 4 + nt) * 32 + lane];
    __syncthreads();

    int r4 = lane >> 2, c4 = lane & 3;

#pragma unroll 1
    for (int s = 0; s < 8; ++s) {
        int cur = s & 1;
        float4 v;
        if (s < 7)
            v = *(const float4*)&s2b[gi_c * FF + (s + 1) * 16 + lcg * 4];
        uint4 bfn[4];
        if (s < 7) {
#pragma unroll
            for (int nt = 0; nt < 4; ++nt)
                bfn[nt] = g_w2f4[((s + 1) * 16 + wn * 4 + nt) * 32 + lane];
        }

#pragma unroll
        for (int mt = 0; mt < 2; ++mt) {
            int mb = wm * 32 + mt * 16 + r4;
            u32 ah0 = AhS[cur][c4 * AST + mb];
            u32 ah1 = AhS[cur][c4 * AST + mb + 8];
            u32 ah2 = AhS[cur][(c4 + 4) * AST + mb];
            u32 ah3 = AhS[cur][(c4 + 4) * AST + mb + 8];
            u32 al0 = AlS[cur][c4 * AST + mb];
            u32 al1 = AlS[cur][c4 * AST + mb + 8];
            u32 al2 = AlS[cur][(c4 + 4) * AST + mb];
            u32 al3 = AlS[cur][(c4 + 4) * AST + mb + 8];
#pragma unroll
            for (int nt = 0; nt < 4; ++nt) {
                uint4 bb = bfc[nt];
                mma16(acc[mt][nt], ah0, ah1, ah2, ah3, bb.x, bb.y);
                mma16(acc[mt][nt], ah0, ah1, ah2, ah3, bb.z, bb.w);
                mma16(acc[mt][nt], al0, al1, al2, al3, bb.x, bb.y);
            }
        }
        if (s < 7) {
            int nb = (s + 1) & 1;
            u32 h01 = packbf2(v.x, v.y), h23 = packbf2(v.z, v.w);
            AhS[nb][(lcg * 2 + 0) * AST + lm] = h01;
            AhS[nb][(lcg * 2 + 1) * AST + lm] = h23;
            AlS[nb][(lcg * 2 + 0) * AST + lm] = packbf2(v.x - bf_lo(h01), v.y - bf_hi(h01));
            AlS[nb][(lcg * 2 + 1) * AST + lm] = packbf2(v.z - bf_lo(h23), v.w - bf_hi(h23));
        }
#pragma unroll
        for (int nt = 0; nt < 4; ++nt) bfc[nt] = bfn[nt];
        __syncthreads();
    }

    const float* x1b = g_x1 + b * KK * FF;
#pragma unroll
    for (int mt = 0; mt < 2; ++mt) {
#pragma unroll
        for (int nt = 0; nt < 4; ++nt) {
            int m = wm * 32 + mt * 16 + r4;
            int n = wn * 32 + nt * 8 + 2 * c4;
#pragma unroll
            for (int half = 0; half < 2; ++half) {
                int gi = i0 + m + half * 8;
                if (gi < KK) {
                    int base = gi * FF + n;
                    float2 bb = *(const float2*)&b2[base];
                    float2 xx = *(const float2*)&x1b[base];
                    float2 o;
                    o.x = tanhf(acc[mt][nt][half * 2 + 0] + bb.x + xx.x);
                    o.y = tanhf(acc[mt][nt][half * 2 + 1] + bb.y + xx.y);
                    *(float2*)&out[(size_t)b * KK * FF + base] = o;
                }
            }
        }
    }
}

// ---------------- launch ----------------
extern "C" void kernel_launch(void* const* d_in, const int* in_sizes, int n_in,
                              void* d_out, int out_size) {
    const float* feat = (const float*)d_in[0];
    const float* pred = (const float*)d_in[1];
    const float* w1   = (const float*)d_in[2];
    const float* b1   = (const float*)d_in[3];
    const float* w2   = (const float*)d_in[4];
    const float* b2   = (const float*)d_in[5];
    float* out = (float*)d_out;

    const int feat_elems = BB * KK * FF;
    float* out_idx = (out_size >= feat_elems + BB * KK) ? (out + feat_elems) : (float*)0;

    cudaLaunchAttribute pdl[1];
    pdl[0].id = cudaLaunchAttributeProgrammaticStreamSerialization;
    pdl[0].val.programmaticStreamSerializationAllowed = 1;

    setup_kernel<<<28, 1024>>>(pred, w1, w2, out_idx);
    {
        cudaLaunchConfig_t cfg = {};
        cfg.gridDim = dim3((KK + 63) / 64, BB);
        cfg.blockDim = dim3(256);
        cfg.attrs = pdl; cfg.numAttrs = 1;
        cudaLaunchKernelEx(&cfg, gemm1_mma, feat);
    }
    {
        cudaLaunchConfig_t cfg = {};
        cfg.gridDim = dim3(BB * KK / 16);
        cfg.blockDim = dim3(256);
        cfg.attrs = pdl; cfg.numAttrs = 1;
        cudaLaunchKernelEx(&cfg, x1_kernel, b1);
    }
    {
        cudaLaunchConfig_t cfg = {};
        cfg.gridDim = dim3(BB * KK / 16);
        cfg.blockDim = dim3(256);
        cfg.attrs = pdl; cfg.numAttrs = 1;
        cudaLaunchKernelEx(&cfg, s2_kernel);
    }
    {
        cudaLaunchConfig_t cfg = {};
        cfg.gridDim = dim3((KK + 63) / 64, BB);
        cfg.blockDim = dim3(256);
        cfg.attrs = pdl; cfg.numAttrs = 1;
        cudaLaunchKernelEx(&cfg, gemm2_mma, b2, out);
    }
}

// round 15
// speedup vs baseline: 1.2294x; 1.2050x over previous
#include <cuda_runtime.h>
#include <math.h>

#define BB 8
#define CC 512
#define HH 75
#define WW 100
#define PP 7500
#define KK 2000
#define FF 128

typedef unsigned long long u64;
typedef unsigned int u32;

#define CLIP(x) fminf(fmaxf((x), 0.0f), 6.0f)

#define GDC_WAIT()   asm volatile("griddepcontrol.wait;" ::: "memory")
#define GDC_LAUNCH() asm volatile("griddepcontrol.launch_dependents;" ::: "memory")

// pack two f32 into bf16x2: result.lo = lo_elem, result.hi = hi_elem
__device__ __forceinline__ u32 packbf2(float lo_elem, float hi_elem) {
    u32 r;
    asm("cvt.rn.bf16x2.f32 %0, %1, %2;" : "=r"(r) : "f"(hi_elem), "f"(lo_elem));
    return r;
}
__device__ __forceinline__ float bf_lo(u32 p) { return __uint_as_float(p << 16); }
__device__ __forceinline__ float bf_hi(u32 p) { return __uint_as_float(p & 0xFFFF0000u); }

__device__ __forceinline__ void mma16(float* d, u32 a0, u32 a1, u32 a2, u32 a3,
                                      u32 b0, u32 b1) {
    asm volatile(
        "mma.sync.aligned.m16n8k16.row.col.f32.bf16.bf16.f32 "
        "{%0,%1,%2,%3}, {%4,%5,%6,%7}, {%8,%9}, {%0,%1,%2,%3};"
        : "+f"(d[0]), "+f"(d[1]), "+f"(d[2]), "+f"(d[3])
        : "r"(a0), "r"(a1), "r"(a2), "r"(a3), "r"(b0), "r"(b1));
}

// ---------------- scratch ----------------
__device__ int   g_sorted[BB * KK];
__device__ int   g_rank[BB * PP];
__device__ int   g_nbr[BB * KK * 9];
__device__ int   g_ord[BB * KK];    // ranks sorted by plane pixel address
__device__ int   g_pixo[BB * KK];   // plane pixel address, ascending
__device__ float g_t1[BB * KK * FF];
__device__ float g_x1[BB * KK * FF];
__device__ float g_s2[BB * KK * FF];
// bf16 hi/lo fragment tables: entry = {b0_hi, b1_hi, b0_lo, b1_lo}
__device__ uint4 g_w1f4[32 * 16 * 32];
__device__ uint4 g_w2f4[8 * 16 * 32];

// ---------------- block-wide exclusive scan (blockDim == 1024) ----------------
__device__ __forceinline__ int block_excl_scan(int v, int* warp_sums, int tid) {
    int lane = tid & 31, wid = tid >> 5;
    int x = v;
#pragma unroll
    for (int o = 1; o < 32; o <<= 1) {
        int y = __shfl_up_sync(0xFFFFFFFFu, x, o);
        if (lane >= o) x += y;
    }
    if (lane == 31) warp_sums[wid] = x;
    __syncthreads();
    if (wid == 0) {
        int s = warp_sums[lane];
        int orig = s;
#pragma unroll
        for (int o = 1; o < 32; o <<= 1) {
            int y = __shfl_up_sync(0xFFFFFFFFu, s, o);
            if (lane >= o) s += y;
        }
        warp_sums[lane] = s - orig;
    }
    __syncthreads();
    return (x - v) + warp_sums[wid];
}

// ---------------- weight split helper ----------------
__device__ __forceinline__ uint4 split_frag(const float* w, int k0, int n) {
    float v0 = w[k0 * FF + n];
    float v1 = w[(k0 + 1) * FF + n];
    float v2 = w[(k0 + 8) * FF + n];
    float v3 = w[(k0 + 9) * FF + n];
    u32 b0h = packbf2(v0, v1);
    u32 b1h = packbf2(v2, v3);
    u32 b0l = packbf2(v0 - bf_lo(b0h), v1 - bf_hi(b0h));
    u32 b1l = packbf2(v2 - bf_lo(b1h), v3 - bf_hi(b1h));
    return make_uint4(b0h, b1h, b0l, b1l);
}

// ---------------- K1: setup = topk + nbr + pixel-order (blocks 0..7) | weight prep (8..27) ----------------
#define CAND_CAP 4096
__global__ void __launch_bounds__(1024) setup_kernel(const float* __restrict__ pred,
                                                     const float* __restrict__ w1,
                                                     const float* __restrict__ w2,
                                                     float* __restrict__ out_idx) {
    int tid = threadIdx.x;
    if (blockIdx.x >= 8) {
        int t = (blockIdx.x - 8) * 1024 + tid;
        if (t < 32 * 16 * 32) {
            int lane = t & 31;
            int ntg  = (t >> 5) & 15;
            int kb   = t >> 9;
            int n  = ntg * 8 + (lane >> 2);
            int k0 = kb * 16 + 2 * (lane & 3);
            g_w1f4[t] = split_frag(w1, k0, n);
        } else if (t < 32 * 16 * 32 + 8 * 16 * 32) {
            int t2 = t - 32 * 16 * 32;
            int lane = t2 & 31;
            int ntg  = (t2 >> 5) & 15;
            int kb   = t2 >> 9;
            int n  = ntg * 8 + (lane >> 2);
            int k0 = kb * 16 + 2 * (lane & 3);
            g_w2f4[t2] = split_frag(w2, k0, n);
        }
        GDC_LAUNCH();
        return;
    }
    // ---- topk ----
    int b = blockIdx.x;
    const float* sc = pred + (size_t)b * 3 * PP;
    __shared__ unsigned keys[PP];
    __shared__ unsigned hist[256];
    __shared__ unsigned short cand[CAND_CAP];
    __shared__ int candN;
    __shared__ int sh_bin;
    __shared__ unsigned sh_r2;
    __shared__ int warp_sums[32];
    __shared__ int rankS[PP];

    for (int i = tid; i < PP; i += 1024) {
        unsigned u = __float_as_uint(sc[i]);
        u = (u & 0x80000000u) ? ~u : (u | 0x80000000u);
        keys[i] = u;
    }
    for (int i = tid; i < PP; i += 1024) rankS[i] = -1;
    if (tid == 0) candN = 0;
    __syncthreads();

    // pass 0 over all keys
    unsigned prefix = 0, r = KK;
    {
        for (int i = tid; i < 256; i += 1024) hist[i] = 0;
        __syncthreads();
        for (int i = tid; i < PP; i += 1024)
            atomicAdd(&hist[keys[i] >> 24], 1u);
        __syncthreads();
        int v = (tid < 256) ? (int)hist[255 - tid] : 0;
        int ex = block_excl_scan(v, warp_sums, tid);
        if (tid < 256 && ex < (int)r && ex + v >= (int)r) {
            sh_bin = 255 - tid;
            sh_r2  = r - (unsigned)ex;
        }
        __syncthreads();
        prefix = ((unsigned)sh_bin) << 24;
        r = sh_r2;
        __syncthreads();
    }
    // compact candidates matching pass-0 bin
    {
        unsigned bin0 = prefix >> 24;
        for (int i = tid; i < PP; i += 1024) {
            if ((keys[i] >> 24) == bin0) {
                int p = atomicAdd(&candN, 1);
                if (p < CAND_CAP) cand[p] = (unsigned short)i;
            }
        }
        __syncthreads();
    }
    int useCand = (candN <= CAND_CAP);
    int nScan = useCand ? candN : PP;

    // passes 1..3 over compacted candidates
#pragma unroll
    for (int pass = 1; pass < 4; ++pass) {
        int shift = 24 - 8 * pass;
        unsigned mask_hi = 0xFFFFFFFFu << (shift + 8);
        for (int i = tid; i < 256; i += 1024) hist[i] = 0;
        __syncthreads();
        for (int idx = tid; idx < nScan; idx += 1024) {
            int i = useCand ? (int)cand[idx] : idx;
            unsigned u = keys[i];
            if ((u & mask_hi) == prefix)
                atomicAdd(&hist[(u >> shift) & 255u], 1u);
        }
        __syncthreads();
        int v = (tid < 256) ? (int)hist[255 - tid] : 0;
        int ex = block_excl_scan(v, warp_sums, tid);
        if (tid < 256 && ex < (int)r && ex + v >= (int)r) {
            sh_bin = 255 - tid;
            sh_r2  = r - (unsigned)ex;
        }
        __syncthreads();
        prefix |= ((unsigned)sh_bin) << shift;
        r = sh_r2;
        __syncthreads();
    }
    unsigned T = prefix;

    int start = tid * 8;
    int cnt_gt = 0, cnt_eq = 0;
#pragma unroll
    for (int k = 0; k < 8; ++k) {
        int i = start + k;
        if (i < PP) {
            unsigned u = keys[i];
            cnt_gt += (u > T);
            cnt_eq += (u == T);
        }
    }
    int base_eq = block_excl_scan(cnt_eq, warp_sums, tid);
    __syncthreads();
    int need = (int)r - base_eq;
    if (need < 0) need = 0;
    if (need > cnt_eq) need = cnt_eq;
    int my_sel = cnt_gt + need;
    int base_out = block_excl_scan(my_sel, warp_sums, tid);

    int pos = base_out, eqr = base_eq;
    for (int k = 0; k < 8; ++k) {
        int i = start + k;
        if (i >= PP) break;
        unsigned u = keys[i];
        bool sel = (u > T);
        if (u == T) { if (eqr < (int)r) sel = true; eqr++; }
        if (sel) {
            g_sorted[b * KK + pos] = i;
            if (out_idx) out_idx[b * KK + pos] = (float)i;
            g_rank[b * PP + i] = pos;
            rankS[i] = pos;
            pos++;
        }
    }
    __syncthreads();

    // ---- nbr (fused) ----
    for (int i = tid; i < KK; i += 1024) {
        int s = g_sorted[b * KK + i];
        int py = s / WW, px = s % WW;
        int* nb = g_nbr + (b * KK + i) * 9;
#pragma unroll
        for (int q = 0; q < 9; ++q) {
            int dy = q / 3 - 1, dx = q % 3 - 1;
            int ny = py + dy, nx = px + dx;
            int v = -1;
            if (ny >= 0 && ny < HH && nx >= 0 && nx < WW)
                v = rankS[ny * WW + nx];
            nb[q] = v;
        }
    }
    __syncthreads();

    // ---- pixel-sorted ordering: ranks sorted by plane address p ----
    // plane addr p = y*100 + x where y=s%75, x=s/75  =>  s(p) = (p%100)*75 + p/100
    {
        int cnt = 0;
#pragma unroll
        for (int k = 0; k < 8; ++k) {
            int p = start + k;
            if (p < PP) {
                int s = (p % WW) * HH + p / WW;
                cnt += (rankS[s] >= 0);
            }
        }
        int base = block_excl_scan(cnt, warp_sums, tid);
        int posn = base;
#pragma unroll
        for (int k = 0; k < 8; ++k) {
            int p = start + k;
            if (p < PP) {
                int s = (p % WW) * HH + p / WW;
                int rk = rankS[s];
                if (rk >= 0) {
                    g_ord[b * KK + posn] = rk;
                    g_pixo[b * KK + posn] = p;
                    posn++;
                }
            }
        }
    }
    GDC_LAUNCH();
}

// ---------------- K2: fused gather + GEMM1, pixel-sorted tiles, bf16 3-term ----------------
#define AST 72
__global__ void __launch_bounds__(256, 2) gemm1_mma(const float* __restrict__ feat) {
    GDC_WAIT();
    __shared__ u32 AhS[2][8 * AST];
    __shared__ u32 AlS[2][8 * AST];
    __shared__ int pixS[64];
    __shared__ int ordS[64];
    int b = blockIdx.y, i0 = blockIdx.x * 64;
    int tid = threadIdx.x;
    int lane = tid & 31, warp = tid >> 5;
    int wm = warp & 1, wn = warp >> 1;
    int lm = tid & 63, lcg = tid >> 6;

    if (tid < 64) {
        int gi = i0 + tid;
        pixS[tid] = (gi < KK) ? g_pixo[b * KK + gi] : 0;
        ordS[tid] = (gi < KK) ? g_ord[b * KK + gi] : 0;
    }
    __syncthreads();

    const float* fb = feat + (size_t)b * CC * PP;
    float acc[2][4][4];
#pragma unroll
    for (int mt = 0; mt < 2; ++mt)
#pragma unroll
        for (int nt = 0; nt < 4; ++nt)
#pragma unroll
            for (int e = 0; e < 4; ++e) acc[mt][nt][e] = 0.0f;

    int mypix = pixS[lm];
    float pf[2][4];

    // prologue: stage 0 straight to smem buffer 0
    {
        const float* fp = fb + (size_t)(lcg * 4) * PP + mypix;
        float v0 = CLIP(fp[0]);
        float v1 = CLIP(fp[PP]);
        float v2 = CLIP(fp[2 * PP]);
        float v3 = CLIP(fp[3 * PP]);
        u32 h01 = packbf2(v0, v1), h23 = packbf2(v2, v3);
        AhS[0][(lcg * 2 + 0) * AST + lm] = h01;
        AhS[0][(lcg * 2 + 1) * AST + lm] = h23;
        AlS[0][(lcg * 2 + 0) * AST + lm] = packbf2(v0 - bf_lo(h01), v1 - bf_hi(h01));
        AlS[0][(lcg * 2 + 1) * AST + lm] = packbf2(v2 - bf_lo(h23), v3 - bf_hi(h23));
    }
    // prologue: stage 1 into pf[1]
    {
        const float* fp = fb + (size_t)(16 + lcg * 4) * PP + mypix;
        pf[1][0] = CLIP(fp[0]);
        pf[1][1] = CLIP(fp[PP]);
        pf[1][2] = CLIP(fp[2 * PP]);
        pf[1][3] = CLIP(fp[3 * PP]);
    }
    // prologue: B frags for stage 0
    uint4 bfc[4];
#pragma unroll
    for (int nt = 0; nt < 4; ++nt)
        bfc[nt] = g_w1f4[(wn * 4 + nt) * 32 + lane];
    __syncthreads();

    int r4 = lane >> 2, c4 = lane & 3;

#pragma unroll 2
    for (int s = 0; s < 32; ++s) {
        int cur = s & 1;
        // issue gathers for stage s+2 into pf[cur]
        if (s < 30) {
            const float* fp = fb + (size_t)((s + 2) * 16 + lcg * 4) * PP + mypix;
            pf[cur][0] = CLIP(fp[0]);
            pf[cur][1] = CLIP(fp[PP]);
            pf[cur][2] = CLIP(fp[2 * PP]);
            pf[cur][3] = CLIP(fp[3 * PP]);
        }
        // prefetch B frags for stage s+1
        uint4 bfn[4];
        if (s < 31) {
#pragma unroll
            for (int nt = 0; nt < 4; ++nt)
                bfn[nt] = g_w1f4[((s + 1) * 16 + wn * 4 + nt) * 32 + lane];
        }

#pragma unroll
        for (int mt = 0; mt < 2; ++mt) {
            int mb = wm * 32 + mt * 16 + r4;
            u32 ah0 = AhS[cur][c4 * AST + mb];
            u32 ah1 = AhS[cur][c4 * AST + mb + 8];
            u32 ah2 = AhS[cur][(c4 + 4) * AST + mb];
            u32 ah3 = AhS[cur][(c4 + 4) * AST + mb + 8];
            u32 al0 = AlS[cur][c4 * AST + mb];
            u32 al1 = AlS[cur][c4 * AST + mb + 8];
            u32 al2 = AlS[cur][(c4 + 4) * AST + mb];
            u32 al3 = AlS[cur][(c4 + 4) * AST + mb + 8];
#pragma unroll
            for (int nt = 0; nt < 4; ++nt) {
                uint4 bb = bfc[nt];
                mma16(acc[mt][nt], ah0, ah1, ah2, ah3, bb.x, bb.y);
                mma16(acc[mt][nt], ah0, ah1, ah2, ah3, bb.z, bb.w);
                mma16(acc[mt][nt], al0, al1, al2, al3, bb.x, bb.y);
            }
        }
        // store stage s+1 (held in pf[cur^1]) into smem buffer cur^1
        if (s < 31) {
            float v0 = pf[cur ^ 1][0], v1 = pf[cur ^ 1][1];
            float v2 = pf[cur ^ 1][2], v3 = pf[cur ^ 1][3];
            u32 h01 = packbf2(v0, v1), h23 = packbf2(v2, v3);
            AhS[cur ^ 1][(lcg * 2 + 0) * AST + lm] = h01;
            AhS[cur ^ 1][(lcg * 2 + 1) * AST + lm] = h23;
            AlS[cur ^ 1][(lcg * 2 + 0) * AST + lm] = packbf2(v0 - bf_lo(h01), v1 - bf_hi(h01));
            AlS[cur ^ 1][(lcg * 2 + 1) * AST + lm] = packbf2(v2 - bf_lo(h23), v3 - bf_hi(h23));
        }
#pragma unroll
        for (int nt = 0; nt < 4; ++nt) bfc[nt] = bfn[nt];
        __syncthreads();
    }

    // epilogue: scatter rows to their rank positions
    float* t1b = g_t1 + b * KK * FF;
#pragma unroll
    for (int mt = 0; mt < 2; ++mt) {
#pragma unroll
        for (int nt = 0; nt < 4; ++nt) {
            int m = wm * 32 + mt * 16 + r4;
            int n = wn * 32 + nt * 8 + 2 * c4;
            if (i0 + m < KK) {
                int row = ordS[m];
                *(float2*)&t1b[row * FF + n] = make_float2(acc[mt][nt][0], acc[mt][nt][1]);
            }
            if (i0 + m + 8 < KK) {
                int row = ordS[m + 8];
                *(float2*)&t1b[row * FF + n] = make_float2(acc[mt][nt][2], acc[mt][nt][3]);
            }
        }
    }
    GDC_LAUNCH();
}

// ---------------- K3: x1 = A @ t1 + b1 (2 rows per thread) ----------------
__global__ void __launch_bounds__(256) x1_kernel(const float* __restrict__ b1) {
    int wid = threadIdx.x >> 5;
    int lane = threadIdx.x & 31;
    int r0 = blockIdx.x * 16 + wid * 2;
    int b = r0 / KK;
    float4 s0 = *(const float4*)&b1[(r0 % KK) * FF + lane * 4];
    float4 s1 = *(const float4*)&b1[((r0 + 1) % KK) * FF + lane * 4];
    GDC_WAIT();
    const float* t1b = g_t1 + b * KK * FF;
#pragma unroll
    for (int rr = 0; rr < 2; ++rr) {
        int r = r0 + rr;
        const int* nb = g_nbr + r * 9;
        float4 s = rr ? s1 : s0;
#pragma unroll
        for (int q = 0; q < 9; ++q) {
            int j = nb[q];
            if (j >= 0) {
                float4 t = *(const float4*)&t1b[j * FF + lane * 4];
                s.x += t.x; s.y += t.y; s.z += t.z; s.w += t.w;
            }
        }
        *(float4*)&g_x1[r * FF + lane * 4] = s;
    }
    GDC_LAUNCH();
}

// ---------------- K4: s2 = A @ x1 (2 rows per thread) ----------------
__global__ void __launch_bounds__(256) s2_kernel() {
    GDC_WAIT();
    int wid = threadIdx.x >> 5;
    int lane = threadIdx.x & 31;
    int r0 = blockIdx.x * 16 + wid * 2;
    int b = r0 / KK;
    const float* x1b = g_x1 + b * KK * FF;
#pragma unroll
    for (int rr = 0; rr < 2; ++rr) {
        int r = r0 + rr;
        const int* nb = g_nbr + r * 9;
        float4 s = make_float4(0.f, 0.f, 0.f, 0.f);
#pragma unroll
        for (int q = 0; q < 9; ++q) {
            int j = nb[q];
            if (j >= 0) {
                float4 t = *(const float4*)&x1b[j * FF + lane * 4];
                s.x += t.x; s.y += t.y; s.z += t.z; s.w += t.w;
            }
        }
        *(float4*)&g_s2[r * FF + lane * 4] = s;
    }
    GDC_LAUNCH();
}

// ---------------- K5: out = tanh(s2 @ w2 + b2 + x1), bf16 3-term, prefetched ----------------
__global__ void __launch_bounds__(256, 2) gemm2_mma(const float* __restrict__ b2,
                                                    float* __restrict__ out) {
    GDC_WAIT();
    __shared__ u32 AhS[2][8 * AST];
    __shared__ u32 AlS[2][8 * AST];
    int b = blockIdx.y, i0 = blockIdx.x * 64;
    int tid = threadIdx.x;
    int lane = tid & 31, warp = tid >> 5;
    int wm = warp & 1, wn = warp >> 1;
    int lm = tid & 63, lcg = tid >> 6;

    const float* s2b = g_s2 + b * KK * FF;
    int gi_l = i0 + lm;
    int gi_c = (gi_l < KK) ? gi_l : (KK - 1);

    float acc[2][4][4];
#pragma unroll
    for (int mt = 0; mt < 2; ++mt)
#pragma unroll
        for (int nt = 0; nt < 4; ++nt)
#pragma unroll
            for (int e = 0; e < 4; ++e) acc[mt][nt][e] = 0.0f;

    // prologue stage 0
    {
        float4 v = *(const float4*)&s2b[gi_c * FF + lcg * 4];
        u32 h01 = packbf2(v.x, v.y), h23 = packbf2(v.z, v.w);
        AhS[0][(lcg * 2 + 0) * AST + lm] = h01;
        AhS[0][(lcg * 2 + 1) * AST + lm] = h23;
        AlS[0][(lcg * 2 + 0) * AST + lm] = packbf2(v.x - bf_lo(h01), v.y - bf_hi(h01));
        AlS[0][(lcg * 2 + 1) * AST + lm] = packbf2(v.z - bf_lo(h23), v.w - bf_hi(h23));
    }
    uint4 bfc[4];
#pragma unroll
    for (int nt = 0; nt < 4; ++nt)
        bfc[nt] = g_w2f4[(wn * 4 + nt) * 32 + lane];
    __syncthreads();

    int r4 = lane >> 2, c4 = lane & 3;

#pragma unroll 1
    for (int s = 0; s < 8; ++s) {
        int cur = s & 1;
        float4 v;
        if (s < 7)
            v = *(const float4*)&s2b[gi_c * FF + (s + 1) * 16 + lcg * 4];
        uint4 bfn[4];
        if (s < 7) {
#pragma unroll
            for (int nt = 0; nt < 4; ++nt)
                bfn[nt] = g_w2f4[((s + 1) * 16 + wn * 4 + nt) * 32 + lane];
        }

#pragma unroll
        for (int mt = 0; mt < 2; ++mt) {
            int mb = wm * 32 + mt * 16 + r4;
            u32 ah0 = AhS[cur][c4 * AST + mb];
            u32 ah1 = AhS[cur][c4 * AST + mb + 8];
            u32 ah2 = AhS[cur][(c4 + 4) * AST + mb];
            u32 ah3 = AhS[cur][(c4 + 4) * AST + mb + 8];
            u32 al0 = AlS[cur][c4 * AST + mb];
            u32 al1 = AlS[cur][c4 * AST + mb + 8];
            u32 al2 = AlS[cur][(c4 + 4) * AST + mb];
            u32 al3 = AlS[cur][(c4 + 4) * AST + mb + 8];
#pragma unroll
            for (int nt = 0; nt < 4; ++nt) {
                uint4 bb = bfc[nt];
                mma16(acc[mt][nt], ah0, ah1, ah2, ah3, bb.x, bb.y);
                mma16(acc[mt][nt], ah0, ah1, ah2, ah3, bb.z, bb.w);
                mma16(acc[mt][nt], al0, al1, al2, al3, bb.x, bb.y);
            }
        }
        if (s < 7) {
            int nb = (s + 1) & 1;
            u32 h01 = packbf2(v.x, v.y), h23 = packbf2(v.z, v.w);
            AhS[nb][(lcg * 2 + 0) * AST + lm] = h01;
            AhS[nb][(lcg * 2 + 1) * AST + lm] = h23;
            AlS[nb][(lcg * 2 + 0) * AST + lm] = packbf2(v.x - bf_lo(h01), v.y - bf_hi(h01));
            AlS[nb][(lcg * 2 + 1) * AST + lm] = packbf2(v.z - bf_lo(h23), v.w - bf_hi(h23));
        }
#pragma unroll
        for (int nt = 0; nt < 4; ++nt) bfc[nt] = bfn[nt];
        __syncthreads();
    }

    const float* x1b = g_x1 + b * KK * FF;
#pragma unroll
    for (int mt = 0; mt < 2; ++mt) {
#pragma unroll
        for (int nt = 0; nt < 4; ++nt) {
            int m = wm * 32 + mt * 16 + r4;
            int n = wn * 32 + nt * 8 + 2 * c4;
#pragma unroll
            for (int half = 0; half < 2; ++half) {
                int gi = i0 + m + half * 8;
                if (gi < KK) {
                    int base = gi * FF + n;
                    float2 bb = *(const float2*)&b2[base];
                    float2 xx = *(const float2*)&x1b[base];
                    float2 o;
                    o.x = tanhf(acc[mt][nt][half * 2 + 0] + bb.x + xx.x);
                    o.y = tanhf(acc[mt][nt][half * 2 + 1] + bb.y + xx.y);
                    *(float2*)&out[(size_t)b * KK * FF + base] = o;
                }
            }
        }
    }
}

// ---------------- launch ----------------
extern "C" void kernel_launch(void* const* d_in, const int* in_sizes, int n_in,
                              void* d_out, int out_size) {
    const float* feat = (const float*)d_in[0];
    const float* pred = (const float*)d_in[1];
    const float* w1   = (const float*)d_in[2];
    const float* b1   = (const float*)d_in[3];
    const float* w2   = (const float*)d_in[4];
    const float* b2   = (const float*)d_in[5];
    float* out = (float*)d_out;

    const int feat_elems = BB * KK * FF;
    float* out_idx = (out_size >= feat_elems + BB * KK) ? (out + feat_elems) : (float*)0;

    cudaLaunchAttribute pdl[1];
    pdl[0].id = cudaLaunchAttributeProgrammaticStreamSerialization;
    pdl[0].val.programmaticStreamSerializationAllowed = 1;

    setup_kernel<<<28, 1024>>>(pred, w1, w2, out_idx);
    {
        cudaLaunchConfig_t cfg = {};
        cfg.gridDim = dim3((KK + 63) / 64, BB);
        cfg.blockDim = dim3(256);
        cfg.attrs = pdl; cfg.numAttrs = 1;
        cudaLaunchKernelEx(&cfg, gemm1_mma, feat);
    }
    {
        cudaLaunchConfig_t cfg = {};
        cfg.gridDim = dim3(BB * KK / 16);
        cfg.blockDim = dim3(256);
        cfg.attrs = pdl; cfg.numAttrs = 1;
        cudaLaunchKernelEx(&cfg, x1_kernel, b1);
    }
    {
        cudaLaunchConfig_t cfg = {};
        cfg.gridDim = dim3(BB * KK / 16);
        cfg.blockDim = dim3(256);
        cfg.attrs = pdl; cfg.numAttrs = 1;
        cudaLaunchKernelEx(&cfg, s2_kernel);
    }
    {
        cudaLaunchConfig_t cfg = {};
        cfg.gridDim = dim3((KK + 63) / 64, BB);
        cfg.blockDim = dim3(256);
        cfg.attrs = pdl; cfg.numAttrs = 1;
        cudaLaunchKernelEx(&cfg, gemm2_mma, b2, out);
    }
}